// round 2
// baseline (speedup 1.0000x reference)
#include <cuda_runtime.h>
#include <math.h>

// Problem constants (SingleLayerMoE_62878321214325): B=1, S=1024 -> T=1024,
// H=1024, E=8, I=1024, top-K=2.
#define T_TOK 1024
#define H_DIM 1024
#define N_EXP 8
#define I_DIM 1024
#define TOPK  2

#define ALPHA 1.702f
#define LIMIT 7.0f

// ---------------- scratch (device globals; no allocations allowed) ----------
__device__ int   g_cnt[N_EXP];                    // tokens routed to each expert
__device__ int   g_tok[N_EXP * T_TOK];            // token id per (expert, slot)
__device__ float g_wt [N_EXP * T_TOK];            // router weight per slot
__device__ float g_act[(size_t)N_EXP * T_TOK * I_DIM]; // 32 MB activation scratch

// ---------------- kernel 0: zero counters + output ---------------------------
__global__ void zero_kernel(float* __restrict__ out) {
    int i = blockIdx.x * blockDim.x + threadIdx.x;
    if (i < T_TOK * H_DIM) out[i] = 0.0f;
    if (i < N_EXP) g_cnt[i] = 0;
}

// ---------------- kernel 1: router (block per token) -------------------------
__global__ void router_kernel(const float* __restrict__ x,
                              const float* __restrict__ rw,
                              const float* __restrict__ rb) {
    const int t = blockIdx.x;
    __shared__ float s[N_EXP][128];

    float p[N_EXP];
#pragma unroll
    for (int e = 0; e < N_EXP; e++) p[e] = 0.0f;

    const float* xr = x + (size_t)t * H_DIM;
    for (int h = threadIdx.x; h < H_DIM; h += 128) {
        float xv = xr[h];
#pragma unroll
        for (int e = 0; e < N_EXP; e++) p[e] += xv * rw[e * H_DIM + h];
    }
#pragma unroll
    for (int e = 0; e < N_EXP; e++) s[e][threadIdx.x] = p[e];
    __syncthreads();

    if (threadIdx.x == 0) {
        float l[N_EXP];
        float mx = -1e30f;
#pragma unroll
        for (int e = 0; e < N_EXP; e++) {
            float sum = 0.0f;
            for (int i = 0; i < 128; i++) sum += s[e][i];
            l[e] = sum + rb[e];
            mx = fmaxf(mx, l[e]);
        }
        float den = 0.0f;
        float sc[N_EXP];
#pragma unroll
        for (int e = 0; e < N_EXP; e++) { sc[e] = expf(l[e] - mx); den += sc[e]; }
        float inv = 1.0f / den;
#pragma unroll
        for (int e = 0; e < N_EXP; e++) sc[e] *= inv;

        // top-2 (indices unique; weights NOT renormalized, per reference)
        int i0 = 0;
#pragma unroll
        for (int e = 1; e < N_EXP; e++) if (sc[e] > sc[i0]) i0 = e;
        int i1 = (i0 == 0) ? 1 : 0;
#pragma unroll
        for (int e = 0; e < N_EXP; e++)
            if (e != i0 && sc[e] > sc[i1]) i1 = e;

        int p0 = atomicAdd(&g_cnt[i0], 1);
        g_tok[i0 * T_TOK + p0] = t;
        g_wt [i0 * T_TOK + p0] = sc[i0];
        int p1 = atomicAdd(&g_cnt[i1], 1);
        g_tok[i1 * T_TOK + p1] = t;
        g_wt [i1 * T_TOK + p1] = sc[i1];
    }
}

// ---------------- kernel 2: gate_up GEMM + fused GLU -------------------------
// C_gate[m,n] = sum_k x[tok[m],k] * gup[e][k][n]
// C_up  [m,n] = sum_k x[tok[m],k] * gup[e][k][n + I]
// act[m,n] = (clip(up)+1) * glu(min(gate,LIMIT))
// Tiles: BM=BN=64, BK=16, 256 threads, 4x4 per thread, dual accumulators.
__global__ __launch_bounds__(256)
void gemm_gateup_kernel(const float* __restrict__ x,
                        const float* __restrict__ gup,
                        const float* __restrict__ gub) {
    const int e   = blockIdx.z;
    const int cnt = g_cnt[e];
    const int m0  = blockIdx.x * 64;
    if (m0 >= cnt) return;
    const int n0  = blockIdx.y * 64;

    __shared__ float As[64][17];   // [m][k], padded
    __shared__ float Bg[16][64];   // [k][n]
    __shared__ float Bu[16][64];

    const int tid = threadIdx.x;
    const int tx  = tid & 15;      // column group
    const int ty  = tid >> 4;      // row group

    // token ids for the 4 A rows this thread loads (fixed across k-steps)
    int tokL[4];
#pragma unroll
    for (int l = 0; l < 4; l++) {
        int m  = (l * 256 + tid) >> 4;
        int gm = m0 + m;
        tokL[l] = (gm < cnt) ? g_tok[e * T_TOK + gm] : -1;
    }

    const float* gupe = gup + (size_t)e * H_DIM * (2 * I_DIM);

    float accG[4][4], accU[4][4];
#pragma unroll
    for (int i = 0; i < 4; i++)
#pragma unroll
        for (int j = 0; j < 4; j++) { accG[i][j] = 0.0f; accU[i][j] = 0.0f; }

    for (int k0 = 0; k0 < H_DIM; k0 += 16) {
#pragma unroll
        for (int l = 0; l < 4; l++) {
            int idx = l * 256 + tid;
            int m = idx >> 4, k = idx & 15;
            As[m][k] = (tokL[l] >= 0) ? x[(size_t)tokL[l] * H_DIM + k0 + k] : 0.0f;
        }
#pragma unroll
        for (int l = 0; l < 4; l++) {
            int idx = l * 256 + tid;
            int k = idx >> 6, n = idx & 63;
            const float* bp = gupe + (size_t)(k0 + k) * (2 * I_DIM) + n0 + n;
            Bg[k][n] = bp[0];
            Bu[k][n] = bp[I_DIM];
        }
        __syncthreads();

#pragma unroll
        for (int kk = 0; kk < 16; kk++) {
            float a[4], bg[4], bu[4];
#pragma unroll
            for (int i = 0; i < 4; i++) a[i] = As[ty * 4 + i][kk];
#pragma unroll
            for (int j = 0; j < 4; j++) { bg[j] = Bg[kk][tx * 4 + j]; bu[j] = Bu[kk][tx * 4 + j]; }
#pragma unroll
            for (int i = 0; i < 4; i++)
#pragma unroll
                for (int j = 0; j < 4; j++) {
                    accG[i][j] += a[i] * bg[j];
                    accU[i][j] += a[i] * bu[j];
                }
        }
        __syncthreads();
    }

    // fused bias + clamped GLU epilogue
#pragma unroll
    for (int i = 0; i < 4; i++) {
        int gm = m0 + ty * 4 + i;
        if (gm >= cnt) continue;
        float* actrow = g_act + (size_t)(e * T_TOK + gm) * I_DIM;
#pragma unroll
        for (int j = 0; j < 4; j++) {
            int n = n0 + tx * 4 + j;
            float g = accG[i][j] + gub[e * 2 * I_DIM + n];
            float u = accU[i][j] + gub[e * 2 * I_DIM + I_DIM + n];
            g = fminf(g, LIMIT);
            u = fminf(fmaxf(u, -LIMIT), LIMIT);
            float glu = g / (1.0f + expf(-ALPHA * g));
            actrow[n] = (u + 1.0f) * glu;
        }
    }
}

// ---------------- kernel 3: down GEMM + weighted combine ---------------------
__global__ __launch_bounds__(256)
void gemm_down_kernel(const float* __restrict__ dwn,
                      const float* __restrict__ dnb,
                      float* __restrict__ out) {
    const int e   = blockIdx.z;
    const int cnt = g_cnt[e];
    const int m0  = blockIdx.x * 64;
    if (m0 >= cnt) return;
    const int n0  = blockIdx.y * 64;

    __shared__ float As[64][17];
    __shared__ float Bs[16][64];

    const int tid = threadIdx.x;
    const int tx  = tid & 15;
    const int ty  = tid >> 4;

    const float* dwe = dwn + (size_t)e * I_DIM * H_DIM;

    float acc[4][4];
#pragma unroll
    for (int i = 0; i < 4; i++)
#pragma unroll
        for (int j = 0; j < 4; j++) acc[i][j] = 0.0f;

    for (int k0 = 0; k0 < I_DIM; k0 += 16) {
#pragma unroll
        for (int l = 0; l < 4; l++) {
            int idx = l * 256 + tid;
            int m = idx >> 4, k = idx & 15;
            int gm = m0 + m;
            As[m][k] = (gm < cnt)
                ? g_act[(size_t)(e * T_TOK + gm) * I_DIM + k0 + k] : 0.0f;
        }
#pragma unroll
        for (int l = 0; l < 4; l++) {
            int idx = l * 256 + tid;
            int k = idx >> 6, n = idx & 63;
            Bs[k][n] = dwe[(size_t)(k0 + k) * H_DIM + n0 + n];
        }
        __syncthreads();

#pragma unroll
        for (int kk = 0; kk < 16; kk++) {
            float a[4], b[4];
#pragma unroll
            for (int i = 0; i < 4; i++) a[i] = As[ty * 4 + i][kk];
#pragma unroll
            for (int j = 0; j < 4; j++) b[j] = Bs[kk][tx * 4 + j];
#pragma unroll
            for (int i = 0; i < 4; i++)
#pragma unroll
                for (int j = 0; j < 4; j++) acc[i][j] += a[i] * b[j];
        }
        __syncthreads();
    }

#pragma unroll
    for (int i = 0; i < 4; i++) {
        int gm = m0 + ty * 4 + i;
        if (gm >= cnt) continue;
        int   tok = g_tok[e * T_TOK + gm];
        float w   = g_wt [e * T_TOK + gm];
#pragma unroll
        for (int j = 0; j < 4; j++) {
            int n = n0 + tx * 4 + j;
            float v = (acc[i][j] + dnb[e * H_DIM + n]) * w;
            // exactly two commutative contributions per element -> deterministic
            atomicAdd(&out[(size_t)tok * H_DIM + n], v);
        }
    }
}

// ---------------- launch -----------------------------------------------------
extern "C" void kernel_launch(void* const* d_in, const int* in_sizes, int n_in,
                              void* d_out, int out_size) {
    const float* x   = (const float*)d_in[0];  // hidden_states [1,1024,1024]
    const float* rw  = (const float*)d_in[1];  // router_weight [8,1024]
    const float* rb  = (const float*)d_in[2];  // router_bias   [8]
    const float* gup = (const float*)d_in[3];  // gate_up_proj  [8,1024,2048]
    const float* gub = (const float*)d_in[4];  // gate_up_bias  [8,2048]
    const float* dwn = (const float*)d_in[5];  // down_proj     [8,1024,1024]
    const float* dnb = (const float*)d_in[6];  // down_bias     [8,1024]
    float* out = (float*)d_out;                // [1,1024,1024] f32

    zero_kernel<<<(T_TOK * H_DIM + 255) / 256, 256>>>(out);
    router_kernel<<<T_TOK, 128>>>(x, rw, rb);

    dim3 g1(T_TOK / 64, I_DIM / 64, N_EXP);   // worst-case grid; blocks self-prune
    gemm_gateup_kernel<<<g1, 256>>>(x, gup, gub);

    dim3 g2(T_TOK / 64, H_DIM / 64, N_EXP);
    gemm_down_kernel<<<g2, 256>>>(dwn, dnb, out);
}

// round 4
// speedup vs baseline: 1.8923x; 1.8923x over previous
#include <cuda_runtime.h>
#include <cstdint>
#include <math.h>

#define T_TOK 1024
#define H_DIM 1024
#define N_EXP 8
#define I_DIM 1024
#define ALPHA 1.702f
#define LIMIT 7.0f

// ---------------- device scratch (no allocations allowed) --------------------
__device__ int      g_cnt[N_EXP];
__device__ int      g_tok[N_EXP * T_TOK];
__device__ float    g_wt [N_EXP * T_TOK];
// activation as packed bf16x2 hi/lo planes: [e*T_TOK + slot][I_DIM/2]
__device__ uint32_t g_act_hi[(size_t)N_EXP * T_TOK * I_DIM / 2];
__device__ uint32_t g_act_lo[(size_t)N_EXP * T_TOK * I_DIM / 2];

// ---------------- helpers ----------------------------------------------------
__device__ __forceinline__ uint32_t smem_u32(const void* p) {
    uint32_t a;
    asm("{ .reg .u64 t; cvta.to.shared.u64 t, %1; cvt.u32.u64 %0, t; }"
        : "=r"(a) : "l"(p));
    return a;
}
__device__ __forceinline__ uint32_t swz(uint32_t off) { return off ^ ((off >> 3) & 0x70); }

__device__ __forceinline__ uint32_t pack_bf16x2(float a, float b) {
    uint32_t r;
    asm("cvt.rn.bf16x2.f32 %0, %1, %2;" : "=r"(r) : "f"(b), "f"(a));
    return r;
}
// split a,b into bf16 hi plane + bf16 residual (lo) plane, both packed x2
__device__ __forceinline__ void split2(float a, float b, uint32_t& hi, uint32_t& lo) {
    hi = pack_bf16x2(a, b);
    float ra = __uint_as_float(hi << 16);
    float rb = __uint_as_float(hi & 0xFFFF0000u);
    lo = pack_bf16x2(a - ra, b - rb);
}

__device__ __forceinline__ void ldsm4(uint32_t* r, uint32_t a) {
    asm volatile("ldmatrix.sync.aligned.m8n8.x4.shared.b16 {%0,%1,%2,%3}, [%4];"
        : "=r"(r[0]), "=r"(r[1]), "=r"(r[2]), "=r"(r[3]) : "r"(a));
}
__device__ __forceinline__ void ldsm4t(uint32_t* r, uint32_t a) {
    asm volatile("ldmatrix.sync.aligned.m8n8.x4.trans.shared.b16 {%0,%1,%2,%3}, [%4];"
        : "=r"(r[0]), "=r"(r[1]), "=r"(r[2]), "=r"(r[3]) : "r"(a));
}
__device__ __forceinline__ void mma16816(float* c, const uint32_t* a, uint32_t b0, uint32_t b1) {
    asm volatile("mma.sync.aligned.m16n8k16.row.col.f32.bf16.bf16.f32 "
        "{%0,%1,%2,%3}, {%4,%5,%6,%7}, {%8,%9}, {%0,%1,%2,%3};"
        : "+f"(c[0]), "+f"(c[1]), "+f"(c[2]), "+f"(c[3])
        : "r"(a[0]), "r"(a[1]), "r"(a[2]), "r"(a[3]), "r"(b0), "r"(b1));
}

// ---------------- kernel 0: zero ---------------------------------------------
__global__ void zero_kernel(float* __restrict__ out) {
    int i = blockIdx.x * blockDim.x + threadIdx.x;
    if (i < T_TOK * H_DIM) out[i] = 0.0f;
    if (i < N_EXP) g_cnt[i] = 0;
}

// ---------------- kernel 1: router -------------------------------------------
__global__ void router_kernel(const float* __restrict__ x,
                              const float* __restrict__ rw,
                              const float* __restrict__ rb) {
    const int t = blockIdx.x;
    __shared__ float s[N_EXP][128];
    float p[N_EXP];
#pragma unroll
    for (int e = 0; e < N_EXP; e++) p[e] = 0.0f;
    const float* xr = x + (size_t)t * H_DIM;
    for (int h = threadIdx.x; h < H_DIM; h += 128) {
        float xv = xr[h];
#pragma unroll
        for (int e = 0; e < N_EXP; e++) p[e] += xv * rw[e * H_DIM + h];
    }
#pragma unroll
    for (int e = 0; e < N_EXP; e++) s[e][threadIdx.x] = p[e];
    __syncthreads();
    if (threadIdx.x == 0) {
        float l[N_EXP], mx = -1e30f;
#pragma unroll
        for (int e = 0; e < N_EXP; e++) {
            float sum = 0.0f;
            for (int i = 0; i < 128; i++) sum += s[e][i];
            l[e] = sum + rb[e];
            mx = fmaxf(mx, l[e]);
        }
        float den = 0.0f, sc[N_EXP];
#pragma unroll
        for (int e = 0; e < N_EXP; e++) { sc[e] = expf(l[e] - mx); den += sc[e]; }
        float inv = 1.0f / den;
#pragma unroll
        for (int e = 0; e < N_EXP; e++) sc[e] *= inv;
        int i0 = 0;
#pragma unroll
        for (int e = 1; e < N_EXP; e++) if (sc[e] > sc[i0]) i0 = e;
        int i1 = (i0 == 0) ? 1 : 0;
#pragma unroll
        for (int e = 0; e < N_EXP; e++) if (e != i0 && sc[e] > sc[i1]) i1 = e;
        int p0 = atomicAdd(&g_cnt[i0], 1);
        g_tok[i0 * T_TOK + p0] = t; g_wt[i0 * T_TOK + p0] = sc[i0];
        int p1 = atomicAdd(&g_cnt[i1], 1);
        g_tok[i1 * T_TOK + p1] = t; g_wt[i1 * T_TOK + p1] = sc[i1];
    }
}

// ---------------- kernel 2: gate_up HMMA GEMM + fused GLU --------------------
// Per-stage SMEM (32KB): A 16KB ([m=128] rows of 128B: hi k0-31 | lo k0-31),
// BG_HI/BG_LO/BU_HI/BU_LO 4KB each ([k=32] rows of 64 bf16 = 128B).
#define GU_A      0
#define GU_BGH    16384
#define GU_BGL    20480
#define GU_BUH    24576
#define GU_BUL    28672
#define GU_STRIDE 32768

__global__ __launch_bounds__(256, 1)
void moe_gateup_hmma(const float* __restrict__ x,
                     const float* __restrict__ gup,
                     const float* __restrict__ gub) {
    const int e   = blockIdx.z;
    const int cnt = g_cnt[e];
    const int m0  = blockIdx.x * 128;
    if (m0 >= cnt) return;
    const int n0  = blockIdx.y * 64;

    extern __shared__ char dsm[];
    __shared__ int s_tok[128];
    const uint32_t smem0 = smem_u32(dsm);
    const uint32_t dbase = (smem0 + 1023u) & ~1023u;
    char* const cbase = dsm + (dbase - smem0);

    const int tid = threadIdx.x, lane = tid & 31, wid = tid >> 5;
    const int mw = wid >> 1, nw = wid & 1;    // warp tile: m 32 x n 32

    if (tid < 128) {
        int gm = m0 + tid;
        s_tok[tid] = (gm < cnt) ? g_tok[e * T_TOK + gm] : -1;
    }
    __syncthreads();

    const float* gupe = gup + (size_t)e * H_DIM * (2 * I_DIM);

    float cg[2][4][4], cu[2][4][4];
#pragma unroll
    for (int a = 0; a < 2; a++)
#pragma unroll
        for (int b = 0; b < 4; b++)
#pragma unroll
            for (int c = 0; c < 4; c++) { cg[a][b][c] = 0.f; cu[a][b][c] = 0.f; }

    float2 pa[8], pg[4], pu[4];

#define GU_LOAD(it_) do { int k0_ = (it_) * 32;                                              \
    _Pragma("unroll") for (int t = 0; t < 8; t++) {                                          \
        int idx = tid + t * 256; int row = idx >> 4, p = idx & 15;                           \
        int tok = s_tok[row];                                                                \
        pa[t] = (tok >= 0) ? *(const float2*)(x + (size_t)tok * H_DIM + k0_ + 2 * p)         \
                           : make_float2(0.f, 0.f); }                                        \
    _Pragma("unroll") for (int t = 0; t < 4; t++) {                                          \
        int idx = tid + t * 256; int kk = idx >> 5, p = idx & 31;                            \
        const float* bp = gupe + (size_t)(k0_ + kk) * (2 * I_DIM) + n0 + 2 * p;              \
        pg[t] = *(const float2*)bp; pu[t] = *(const float2*)(bp + I_DIM); }                  \
} while (0)

#define GU_STORE(b_) do { char* sb = cbase + (b_) * GU_STRIDE;                               \
    _Pragma("unroll") for (int t = 0; t < 8; t++) {                                          \
        int idx = tid + t * 256; int row = idx >> 4, p = idx & 15;                           \
        uint32_t hi, lo; split2(pa[t].x, pa[t].y, hi, lo);                                   \
        *(uint32_t*)(sb + GU_A + swz(row * 128 + p * 4))      = hi;                          \
        *(uint32_t*)(sb + GU_A + swz(row * 128 + 64 + p * 4)) = lo; }                        \
    _Pragma("unroll") for (int t = 0; t < 4; t++) {                                          \
        int idx = tid + t * 256; int kk = idx >> 5, p = idx & 31;                            \
        uint32_t hg, lg, hu, lu;                                                             \
        split2(pg[t].x, pg[t].y, hg, lg); split2(pu[t].x, pu[t].y, hu, lu);                  \
        uint32_t so = swz(kk * 128 + p * 4);                                                 \
        *(uint32_t*)(sb + GU_BGH + so) = hg; *(uint32_t*)(sb + GU_BGL + so) = lg;            \
        *(uint32_t*)(sb + GU_BUH + so) = hu; *(uint32_t*)(sb + GU_BUL + so) = lu; }          \
} while (0)

#define GU_MMAS(b_) do { uint32_t base = dbase + (b_) * GU_STRIDE;                           \
    _Pragma("unroll") for (int s = 0; s < 2; s++) {                                          \
        uint32_t ah[2][4], al[2][4];                                                         \
        _Pragma("unroll") for (int mt = 0; mt < 2; mt++) {                                   \
            uint32_t row = mw * 32 + mt * 16 + (lane & 15);                                  \
            uint32_t co  = s * 32 + ((lane >> 4) << 4);                                      \
            ldsm4(ah[mt], base + GU_A + swz(row * 128 + co));                                \
            ldsm4(al[mt], base + GU_A + swz(row * 128 + 64 + co)); }                         \
        uint32_t krow = s * 16 + (lane & 15);                                                \
        uint32_t ccol = nw * 64 + ((lane >> 4) << 4);                                        \
        uint32_t bh[8], bl[8];                                                               \
        _Pragma("unroll") for (int h = 0; h < 2; h++) {                                      \
            ldsm4t(bh + 4 * h, base + GU_BGH + swz(krow * 128 + ccol + h * 32));             \
            ldsm4t(bl + 4 * h, base + GU_BGL + swz(krow * 128 + ccol + h * 32)); }           \
        _Pragma("unroll") for (int mt = 0; mt < 2; mt++)                                     \
            _Pragma("unroll") for (int nf = 0; nf < 4; nf++) {                               \
                mma16816(cg[mt][nf], ah[mt], bh[2*nf], bh[2*nf+1]);                          \
                mma16816(cg[mt][nf], ah[mt], bl[2*nf], bl[2*nf+1]);                          \
                mma16816(cg[mt][nf], al[mt], bh[2*nf], bh[2*nf+1]); }                        \
        _Pragma("unroll") for (int h = 0; h < 2; h++) {                                      \
            ldsm4t(bh + 4 * h, base + GU_BUH + swz(krow * 128 + ccol + h * 32));             \
            ldsm4t(bl + 4 * h, base + GU_BUL + swz(krow * 128 + ccol + h * 32)); }           \
        _Pragma("unroll") for (int mt = 0; mt < 2; mt++)                                     \
            _Pragma("unroll") for (int nf = 0; nf < 4; nf++) {                               \
                mma16816(cu[mt][nf], ah[mt], bh[2*nf], bh[2*nf+1]);                          \
                mma16816(cu[mt][nf], ah[mt], bl[2*nf], bl[2*nf+1]);                          \
                mma16816(cu[mt][nf], al[mt], bh[2*nf], bh[2*nf+1]); }                        \
    }                                                                                        \
} while (0)

    GU_LOAD(0);
    GU_STORE(0);
    __syncthreads();
#pragma unroll 1
    for (int it = 0; it < 32; ++it) {
        if (it + 1 < 32) GU_LOAD(it + 1);
        GU_MMAS(it & 1);
        __syncthreads();
        if (it + 1 < 32) { GU_STORE((it + 1) & 1); __syncthreads(); }
    }

    // epilogue: bias + clamped GLU -> g_act (bf16 hi/lo packed)
    const float* gb = gub + e * 2 * I_DIM;
#pragma unroll
    for (int mt = 0; mt < 2; mt++)
#pragma unroll
        for (int r = 0; r < 2; r++) {
            int slot = m0 + mw * 32 + mt * 16 + (lane >> 2) + r * 8;
            if (slot >= cnt) continue;
            size_t abase = ((size_t)(e * T_TOK + slot) * I_DIM) >> 1;
#pragma unroll
            for (int nf = 0; nf < 4; nf++) {
                int col = n0 + nw * 32 + nf * 8 + (lane & 3) * 2;
                float g0 = cg[mt][nf][2 * r]     + gb[col];
                float g1 = cg[mt][nf][2 * r + 1] + gb[col + 1];
                float u0 = cu[mt][nf][2 * r]     + gb[I_DIM + col];
                float u1 = cu[mt][nf][2 * r + 1] + gb[I_DIM + col + 1];
                g0 = fminf(g0, LIMIT); g1 = fminf(g1, LIMIT);
                u0 = fminf(fmaxf(u0, -LIMIT), LIMIT);
                u1 = fminf(fmaxf(u1, -LIMIT), LIMIT);
                float a0 = (u0 + 1.0f) * (g0 / (1.0f + __expf(-ALPHA * g0)));
                float a1 = (u1 + 1.0f) * (g1 / (1.0f + __expf(-ALPHA * g1)));
                uint32_t hi, lo; split2(a0, a1, hi, lo);
                g_act_hi[abase + (col >> 1)] = hi;
                g_act_lo[abase + (col >> 1)] = lo;
            }
        }
#undef GU_LOAD
#undef GU_STORE
#undef GU_MMAS
}

// ---------------- kernel 3: down HMMA GEMM + weighted combine ----------------
// Per-stage SMEM (24KB): A 16KB (hi|lo packed rows), B_HI 4KB, B_LO 4KB.
#define DN_A      0
#define DN_BH     16384
#define DN_BL     20480
#define DN_STRIDE 24576

__global__ __launch_bounds__(256, 1)
void moe_down_hmma(const float* __restrict__ dwn,
                   const float* __restrict__ dnb,
                   float* __restrict__ out) {
    const int e   = blockIdx.z;
    const int cnt = g_cnt[e];
    const int m0  = blockIdx.x * 128;
    if (m0 >= cnt) return;
    const int n0  = blockIdx.y * 64;

    extern __shared__ char dsm[];
    const uint32_t smem0 = smem_u32(dsm);
    const uint32_t dbase = (smem0 + 1023u) & ~1023u;
    char* const cbase = dsm + (dbase - smem0);

    const int tid = threadIdx.x, lane = tid & 31, wid = tid >> 5;
    const int mw = wid >> 1, nw = wid & 1;

    const float* dwe = dwn + (size_t)e * I_DIM * H_DIM;
    const size_t arow0 = (size_t)(e * T_TOK + m0) * (I_DIM / 2);   // u32 units

    float cd[2][4][4];
#pragma unroll
    for (int a = 0; a < 2; a++)
#pragma unroll
        for (int b = 0; b < 4; b++)
#pragma unroll
            for (int c = 0; c < 4; c++) cd[a][b][c] = 0.f;

    uint2 ph[4], pl[4]; float2 pb[4];

#define DN_LOAD(it_) do { int k0_ = (it_) * 32;                                              \
    _Pragma("unroll") for (int t = 0; t < 4; t++) {                                          \
        int idx = tid + t * 256; int row = idx >> 3, p2 = idx & 7;                           \
        size_t gi = arow0 + (size_t)row * (I_DIM / 2) + (k0_ >> 1) + p2 * 2;                 \
        ph[t] = *(const uint2*)(g_act_hi + gi);                                              \
        pl[t] = *(const uint2*)(g_act_lo + gi); }                                            \
    _Pragma("unroll") for (int t = 0; t < 4; t++) {                                          \
        int idx = tid + t * 256; int kk = idx >> 5, p = idx & 31;                            \
        pb[t] = *(const float2*)(dwe + (size_t)(k0_ + kk) * H_DIM + n0 + 2 * p); }           \
} while (0)

#define DN_STORE(b_) do { char* sb = cbase + (b_) * DN_STRIDE;                               \
    _Pragma("unroll") for (int t = 0; t < 4; t++) {                                          \
        int idx = tid + t * 256; int row = idx >> 3, p2 = idx & 7;                           \
        *(uint2*)(sb + DN_A + swz(row * 128 + p2 * 8))      = ph[t];                         \
        *(uint2*)(sb + DN_A + swz(row * 128 + 64 + p2 * 8)) = pl[t]; }                       \
    _Pragma("unroll") for (int t = 0; t < 4; t++) {                                          \
        int idx = tid + t * 256; int kk = idx >> 5, p = idx & 31;                            \
        uint32_t hi, lo; split2(pb[t].x, pb[t].y, hi, lo);                                   \
        uint32_t so = swz(kk * 128 + p * 4);                                                 \
        *(uint32_t*)(sb + DN_BH + so) = hi; *(uint32_t*)(sb + DN_BL + so) = lo; }            \
} while (0)

#define DN_MMAS(b_) do { uint32_t base = dbase + (b_) * DN_STRIDE;                           \
    _Pragma("unroll") for (int s = 0; s < 2; s++) {                                          \
        uint32_t ah[2][4], al[2][4];                                                         \
        _Pragma("unroll") for (int mt = 0; mt < 2; mt++) {                                   \
            uint32_t row = mw * 32 + mt * 16 + (lane & 15);                                  \
            uint32_t co  = s * 32 + ((lane >> 4) << 4);                                      \
            ldsm4(ah[mt], base + DN_A + swz(row * 128 + co));                                \
            ldsm4(al[mt], base + DN_A + swz(row * 128 + 64 + co)); }                         \
        uint32_t krow = s * 16 + (lane & 15);                                                \
        uint32_t ccol = nw * 64 + ((lane >> 4) << 4);                                        \
        uint32_t bh[8], bl[8];                                                               \
        _Pragma("unroll") for (int h = 0; h < 2; h++) {                                      \
            ldsm4t(bh + 4 * h, base + DN_BH + swz(krow * 128 + ccol + h * 32));              \
            ldsm4t(bl + 4 * h, base + DN_BL + swz(krow * 128 + ccol + h * 32)); }            \
        _Pragma("unroll") for (int mt = 0; mt < 2; mt++)                                     \
            _Pragma("unroll") for (int nf = 0; nf < 4; nf++) {                               \
                mma16816(cd[mt][nf], ah[mt], bh[2*nf], bh[2*nf+1]);                          \
                mma16816(cd[mt][nf], ah[mt], bl[2*nf], bl[2*nf+1]);                          \
                mma16816(cd[mt][nf], al[mt], bh[2*nf], bh[2*nf+1]); }                        \
    }                                                                                        \
} while (0)

    DN_LOAD(0);
    DN_STORE(0);
    __syncthreads();
#pragma unroll 1
    for (int it = 0; it < 32; ++it) {
        if (it + 1 < 32) DN_LOAD(it + 1);
        DN_MMAS(it & 1);
        __syncthreads();
        if (it + 1 < 32) { DN_STORE((it + 1) & 1); __syncthreads(); }
    }

    const float* db = dnb + e * H_DIM;
#pragma unroll
    for (int mt = 0; mt < 2; mt++)
#pragma unroll
        for (int r = 0; r < 2; r++) {
            int slot = m0 + mw * 32 + mt * 16 + (lane >> 2) + r * 8;
            if (slot >= cnt) continue;
            int   tok = g_tok[e * T_TOK + slot];
            float w   = g_wt [e * T_TOK + slot];
            float* op = out + (size_t)tok * H_DIM;
#pragma unroll
            for (int nf = 0; nf < 4; nf++) {
                int col = n0 + nw * 32 + nf * 8 + (lane & 3) * 2;
                float v0 = (cd[mt][nf][2 * r]     + db[col])     * w;
                float v1 = (cd[mt][nf][2 * r + 1] + db[col + 1]) * w;
                atomicAdd(op + col,     v0);
                atomicAdd(op + col + 1, v1);
            }
        }
#undef DN_LOAD
#undef DN_STORE
#undef DN_MMAS
}

// ---------------- launch -----------------------------------------------------
extern "C" void kernel_launch(void* const* d_in, const int* in_sizes, int n_in,
                              void* d_out, int out_size) {
    const float* x   = (const float*)d_in[0];
    const float* rw  = (const float*)d_in[1];
    const float* rb  = (const float*)d_in[2];
    const float* gup = (const float*)d_in[3];
    const float* gub = (const float*)d_in[4];
    const float* dwn = (const float*)d_in[5];
    const float* dnb = (const float*)d_in[6];
    float* out = (float*)d_out;

    static bool attr_done = false;
    if (!attr_done) {
        cudaFuncSetAttribute(moe_gateup_hmma, cudaFuncAttributeMaxDynamicSharedMemorySize,
                             2 * GU_STRIDE + 1024);
        cudaFuncSetAttribute(moe_down_hmma, cudaFuncAttributeMaxDynamicSharedMemorySize,
                             2 * DN_STRIDE + 1024);
        attr_done = true;
    }

    zero_kernel<<<(T_TOK * H_DIM + 255) / 256, 256>>>(out);
    router_kernel<<<T_TOK, 128>>>(x, rw, rb);

    dim3 g1(T_TOK / 128, I_DIM / 64, N_EXP);
    moe_gateup_hmma<<<g1, 256, 2 * GU_STRIDE + 1024>>>(x, gup, gub);

    dim3 g2(T_TOK / 128, H_DIM / 64, N_EXP);
    moe_down_hmma<<<g2, 256, 2 * DN_STRIDE + 1024>>>(dwn, dnb, out);
}

// round 5
// speedup vs baseline: 2.0085x; 1.0614x over previous
#include <cuda_runtime.h>
#include <cstdint>
#include <math.h>

#define T_TOK 1024
#define H_DIM 1024
#define N_EXP 8
#define I_DIM 1024
#define ALPHA 1.702f
#define LIMIT 7.0f

// ---------------- device scratch (no allocations allowed) --------------------
__device__ int      g_cnt[N_EXP];
__device__ int      g_tok[N_EXP * T_TOK];
__device__ float    g_wt [N_EXP * T_TOK];
// bf16 hi/lo planes, packed 2 elems per u32 (pair j = elems 2j,2j+1)
__device__ __align__(16) uint32_t g_x_hi  [(size_t)T_TOK * H_DIM / 2];
__device__ __align__(16) uint32_t g_x_lo  [(size_t)T_TOK * H_DIM / 2];
__device__ __align__(16) uint32_t g_gup_hi[(size_t)N_EXP * H_DIM * 2 * I_DIM / 2];
__device__ __align__(16) uint32_t g_gup_lo[(size_t)N_EXP * H_DIM * 2 * I_DIM / 2];
__device__ __align__(16) uint32_t g_dwn_hi[(size_t)N_EXP * I_DIM * H_DIM / 2];
__device__ __align__(16) uint32_t g_dwn_lo[(size_t)N_EXP * I_DIM * H_DIM / 2];
__device__ __align__(16) uint32_t g_act_hi[(size_t)N_EXP * T_TOK * I_DIM / 2];
__device__ __align__(16) uint32_t g_act_lo[(size_t)N_EXP * T_TOK * I_DIM / 2];

// ---------------- helpers ----------------------------------------------------
__device__ __forceinline__ uint32_t smem_u32(const void* p) {
    uint32_t a;
    asm("{ .reg .u64 t; cvta.to.shared.u64 t, %1; cvt.u32.u64 %0, t; }"
        : "=r"(a) : "l"(p));
    return a;
}
__device__ __forceinline__ uint32_t swz(uint32_t off) { return off ^ ((off >> 3) & 0x70); }

__device__ __forceinline__ uint32_t pack_bf16x2(float a, float b) {
    uint32_t r;
    asm("cvt.rn.bf16x2.f32 %0, %1, %2;" : "=r"(r) : "f"(b), "f"(a));
    return r;
}
__device__ __forceinline__ void split2(float a, float b, uint32_t& hi, uint32_t& lo) {
    hi = pack_bf16x2(a, b);
    float ra = __uint_as_float(hi << 16);
    float rb = __uint_as_float(hi & 0xFFFF0000u);
    lo = pack_bf16x2(a - ra, b - rb);
}

__device__ __forceinline__ void ldsm4(uint32_t* r, uint32_t a) {
    asm volatile("ldmatrix.sync.aligned.m8n8.x4.shared.b16 {%0,%1,%2,%3}, [%4];"
        : "=r"(r[0]), "=r"(r[1]), "=r"(r[2]), "=r"(r[3]) : "r"(a));
}
__device__ __forceinline__ void ldsm4t(uint32_t* r, uint32_t a) {
    asm volatile("ldmatrix.sync.aligned.m8n8.x4.trans.shared.b16 {%0,%1,%2,%3}, [%4];"
        : "=r"(r[0]), "=r"(r[1]), "=r"(r[2]), "=r"(r[3]) : "r"(a));
}
__device__ __forceinline__ void mma16816(float* c, const uint32_t* a, uint32_t b0, uint32_t b1) {
    asm volatile("mma.sync.aligned.m16n8k16.row.col.f32.bf16.bf16.f32 "
        "{%0,%1,%2,%3}, {%4,%5,%6,%7}, {%8,%9}, {%0,%1,%2,%3};"
        : "+f"(c[0]), "+f"(c[1]), "+f"(c[2]), "+f"(c[3])
        : "r"(a[0]), "r"(a[1]), "r"(a[2]), "r"(a[3]), "r"(b0), "r"(b1));
}

#define CP16(dst, src) \
    asm volatile("cp.async.cg.shared.global [%0], [%1], 16;" :: "r"(dst), "l"(src) : "memory")
#define CP_COMMIT() asm volatile("cp.async.commit_group;" ::: "memory")
#define CP_WAIT1()  asm volatile("cp.async.wait_group 1;" ::: "memory")

// ---------------- kernel: fp32 -> bf16 hi/lo split planes --------------------
__global__ void convert_kernel(const float4* __restrict__ src,
                               uint2* __restrict__ hi, uint2* __restrict__ lo, int n4) {
    int i = blockIdx.x * blockDim.x + threadIdx.x;
    if (i >= n4) return;
    float4 v = src[i];
    uint32_t h0, l0, h1, l1;
    split2(v.x, v.y, h0, l0);
    split2(v.z, v.w, h1, l1);
    hi[i] = make_uint2(h0, h1);
    lo[i] = make_uint2(l0, l1);
}

// ---------------- kernel 0: zero ---------------------------------------------
__global__ void zero_kernel(float* __restrict__ out) {
    int i = blockIdx.x * blockDim.x + threadIdx.x;
    if (i < T_TOK * H_DIM) out[i] = 0.0f;
    if (i < N_EXP) g_cnt[i] = 0;
}

// ---------------- kernel 1: router -------------------------------------------
__global__ void router_kernel(const float* __restrict__ x,
                              const float* __restrict__ rw,
                              const float* __restrict__ rb) {
    const int t = blockIdx.x;
    __shared__ float s[N_EXP][128];
    float p[N_EXP];
#pragma unroll
    for (int e = 0; e < N_EXP; e++) p[e] = 0.0f;
    const float* xr = x + (size_t)t * H_DIM;
    for (int h = threadIdx.x; h < H_DIM; h += 128) {
        float xv = xr[h];
#pragma unroll
        for (int e = 0; e < N_EXP; e++) p[e] += xv * rw[e * H_DIM + h];
    }
#pragma unroll
    for (int e = 0; e < N_EXP; e++) s[e][threadIdx.x] = p[e];
    __syncthreads();
    if (threadIdx.x == 0) {
        float l[N_EXP], mx = -1e30f;
#pragma unroll
        for (int e = 0; e < N_EXP; e++) {
            float sum = 0.0f;
            for (int i = 0; i < 128; i++) sum += s[e][i];
            l[e] = sum + rb[e];
            mx = fmaxf(mx, l[e]);
        }
        float den = 0.0f, sc[N_EXP];
#pragma unroll
        for (int e = 0; e < N_EXP; e++) { sc[e] = expf(l[e] - mx); den += sc[e]; }
        float inv = 1.0f / den;
#pragma unroll
        for (int e = 0; e < N_EXP; e++) sc[e] *= inv;
        int i0 = 0;
#pragma unroll
        for (int e = 1; e < N_EXP; e++) if (sc[e] > sc[i0]) i0 = e;
        int i1 = (i0 == 0) ? 1 : 0;
#pragma unroll
        for (int e = 0; e < N_EXP; e++) if (e != i0 && sc[e] > sc[i1]) i1 = e;
        int p0 = atomicAdd(&g_cnt[i0], 1);
        g_tok[i0 * T_TOK + p0] = t; g_wt[i0 * T_TOK + p0] = sc[i0];
        int p1 = atomicAdd(&g_cnt[i1], 1);
        g_tok[i1 * T_TOK + p1] = t; g_wt[i1 * T_TOK + p1] = sc[i1];
    }
}

// ---------------- kernel 2: gate_up HMMA (cp.async 3-stage) ------------------
// Stage (32KB): A 16KB (128 rows x [hi 64B | lo 64B]), BGH/BGL/BUH/BUL 4KB each.
#define GU_A      0
#define GU_BGH    16384
#define GU_BGL    20480
#define GU_BUH    24576
#define GU_BUL    28672
#define GU_STRIDE 32768
#define STAGES    3

__global__ __launch_bounds__(256, 1)
void moe_gateup_hmma(const float* __restrict__ gub) {
    const int e   = blockIdx.z;
    const int cnt = g_cnt[e];
    const int m0  = blockIdx.x * 128;
    if (m0 >= cnt) return;
    const int n0  = blockIdx.y * 64;

    extern __shared__ char dsm[];
    __shared__ int s_tok[128];
    const uint32_t dbase = (smem_u32(dsm) + 1023u) & ~1023u;

    const int tid = threadIdx.x, lane = tid & 31, wid = tid >> 5;
    const int mw = wid >> 1, nw = wid & 1;

    if (tid < 128) {
        int gm = m0 + tid;
        s_tok[tid] = (gm < cnt) ? g_tok[e * T_TOK + gm] : g_tok[e * T_TOK]; // clamp
    }
    __syncthreads();

    // per-thread fixed roles
    const int rA  = tid >> 2;            // A rows rA and rA+64
    const int pA  = tid & 3;             // 16B chunk in 64B half-row
    const int tA0 = s_tok[rA], tA1 = s_tok[rA + 64];
    const int kB  = tid >> 3;            // B k-row (0..31)
    const int pB  = tid & 7;             // 16B chunk in 128B row
    const size_t gupb = (size_t)e * (H_DIM * I_DIM);   // u32 units per plane
    const uint32_t dA0h = swz(rA * 128 + pA * 16),        dA0l = swz(rA * 128 + 64 + pA * 16);
    const uint32_t dA1h = swz((rA + 64) * 128 + pA * 16), dA1l = swz((rA + 64) * 128 + 64 + pA * 16);
    const uint32_t dB   = swz(kB * 128 + pB * 16);

#define GU_ISSUE(s_) do { if ((s_) < 32) {                                                  \
    uint32_t bb = dbase + ((s_) % STAGES) * GU_STRIDE;                                       \
    int kh = (s_) * 16;                                                                      \
    CP16(bb + GU_A + dA0h, g_x_hi + (size_t)tA0 * 512 + kh + pA * 4);                        \
    CP16(bb + GU_A + dA0l, g_x_lo + (size_t)tA0 * 512 + kh + pA * 4);                        \
    CP16(bb + GU_A + dA1h, g_x_hi + (size_t)tA1 * 512 + kh + pA * 4);                        \
    CP16(bb + GU_A + dA1l, g_x_lo + (size_t)tA1 * 512 + kh + pA * 4);                        \
    size_t bro = gupb + (size_t)((s_) * 32 + kB) * 1024 + (n0 >> 1) + pB * 4;                \
    CP16(bb + GU_BGH + dB, g_gup_hi + bro);                                                  \
    CP16(bb + GU_BGL + dB, g_gup_lo + bro);                                                  \
    CP16(bb + GU_BUH + dB, g_gup_hi + bro + 512);                                            \
    CP16(bb + GU_BUL + dB, g_gup_lo + bro + 512);                                            \
} CP_COMMIT(); } while (0)

    float cg[2][4][4], cu[2][4][4];
#pragma unroll
    for (int a = 0; a < 2; a++)
#pragma unroll
        for (int b = 0; b < 4; b++)
#pragma unroll
            for (int c = 0; c < 4; c++) { cg[a][b][c] = 0.f; cu[a][b][c] = 0.f; }

    GU_ISSUE(0);
    GU_ISSUE(1);

#pragma unroll 1
    for (int it = 0; it < 32; ++it) {
        CP_WAIT1();
        __syncthreads();
        GU_ISSUE(it + 2);
        uint32_t base = dbase + (it % STAGES) * GU_STRIDE;
#pragma unroll
        for (int s = 0; s < 2; s++) {
            uint32_t ah[2][4], al[2][4];
#pragma unroll
            for (int mt = 0; mt < 2; mt++) {
                uint32_t row = mw * 32 + mt * 16 + (lane & 15);
                uint32_t co  = s * 32 + ((lane >> 4) << 4);
                ldsm4(ah[mt], base + GU_A + swz(row * 128 + co));
                ldsm4(al[mt], base + GU_A + swz(row * 128 + 64 + co));
            }
            uint32_t krow = s * 16 + (lane & 15);
            uint32_t ccol = nw * 64 + ((lane >> 4) << 4);
            uint32_t bh[8], bl[8];
#pragma unroll
            for (int h = 0; h < 2; h++) {
                ldsm4t(bh + 4 * h, base + GU_BGH + swz(krow * 128 + ccol + h * 32));
                ldsm4t(bl + 4 * h, base + GU_BGL + swz(krow * 128 + ccol + h * 32));
            }
#pragma unroll
            for (int mt = 0; mt < 2; mt++)
#pragma unroll
                for (int nf = 0; nf < 4; nf++) {
                    mma16816(cg[mt][nf], ah[mt], bh[2*nf], bh[2*nf+1]);
                    mma16816(cg[mt][nf], ah[mt], bl[2*nf], bl[2*nf+1]);
                    mma16816(cg[mt][nf], al[mt], bh[2*nf], bh[2*nf+1]);
                }
#pragma unroll
            for (int h = 0; h < 2; h++) {
                ldsm4t(bh + 4 * h, base + GU_BUH + swz(krow * 128 + ccol + h * 32));
                ldsm4t(bl + 4 * h, base + GU_BUL + swz(krow * 128 + ccol + h * 32));
            }
#pragma unroll
            for (int mt = 0; mt < 2; mt++)
#pragma unroll
                for (int nf = 0; nf < 4; nf++) {
                    mma16816(cu[mt][nf], ah[mt], bh[2*nf], bh[2*nf+1]);
                    mma16816(cu[mt][nf], ah[mt], bl[2*nf], bl[2*nf+1]);
                    mma16816(cu[mt][nf], al[mt], bh[2*nf], bh[2*nf+1]);
                }
        }
    }
#undef GU_ISSUE

    // epilogue: bias + clamped GLU -> g_act (bf16 hi/lo packed)
    const float* gb = gub + e * 2 * I_DIM;
#pragma unroll
    for (int mt = 0; mt < 2; mt++)
#pragma unroll
        for (int r = 0; r < 2; r++) {
            int slot = m0 + mw * 32 + mt * 16 + (lane >> 2) + r * 8;
            if (slot >= cnt) continue;
            size_t abase = ((size_t)(e * T_TOK + slot) * I_DIM) >> 1;
#pragma unroll
            for (int nf = 0; nf < 4; nf++) {
                int col = n0 + nw * 32 + nf * 8 + (lane & 3) * 2;
                float g0 = cg[mt][nf][2 * r]     + gb[col];
                float g1 = cg[mt][nf][2 * r + 1] + gb[col + 1];
                float u0 = cu[mt][nf][2 * r]     + gb[I_DIM + col];
                float u1 = cu[mt][nf][2 * r + 1] + gb[I_DIM + col + 1];
                g0 = fminf(g0, LIMIT); g1 = fminf(g1, LIMIT);
                u0 = fminf(fmaxf(u0, -LIMIT), LIMIT);
                u1 = fminf(fmaxf(u1, -LIMIT), LIMIT);
                float a0 = (u0 + 1.0f) * (g0 / (1.0f + __expf(-ALPHA * g0)));
                float a1 = (u1 + 1.0f) * (g1 / (1.0f + __expf(-ALPHA * g1)));
                uint32_t hi, lo; split2(a0, a1, hi, lo);
                g_act_hi[abase + (col >> 1)] = hi;
                g_act_lo[abase + (col >> 1)] = lo;
            }
        }
}

// ---------------- kernel 3: down HMMA (cp.async 3-stage) ---------------------
// Stage (24KB): A 16KB, BH 4KB, BL 4KB.
#define DN_A      0
#define DN_BH     16384
#define DN_BL     20480
#define DN_STRIDE 24576

__global__ __launch_bounds__(256, 2)
void moe_down_hmma(const float* __restrict__ dnb, float* __restrict__ out) {
    const int e   = blockIdx.z;
    const int cnt = g_cnt[e];
    const int m0  = blockIdx.x * 128;
    if (m0 >= cnt) return;
    const int n0  = blockIdx.y * 64;

    extern __shared__ char dsm[];
    const uint32_t dbase = (smem_u32(dsm) + 1023u) & ~1023u;

    const int tid = threadIdx.x, lane = tid & 31, wid = tid >> 5;
    const int mw = wid >> 1, nw = wid & 1;

    const int rA = tid >> 2, pA = tid & 3;
    const int kB = tid >> 3, pB = tid & 7;
    const size_t a0 = (size_t)(e * T_TOK + m0 + rA) * 512;
    const size_t a1 = (size_t)(e * T_TOK + m0 + rA + 64) * 512;
    const size_t dwb = (size_t)e * (I_DIM * H_DIM / 2);
    const uint32_t dA0h = swz(rA * 128 + pA * 16),        dA0l = swz(rA * 128 + 64 + pA * 16);
    const uint32_t dA1h = swz((rA + 64) * 128 + pA * 16), dA1l = swz((rA + 64) * 128 + 64 + pA * 16);
    const uint32_t dB   = swz(kB * 128 + pB * 16);

#define DN_ISSUE(s_) do { if ((s_) < 32) {                                                   \
    uint32_t bb = dbase + ((s_) % STAGES) * DN_STRIDE;                                       \
    int kh = (s_) * 16;                                                                      \
    CP16(bb + DN_A + dA0h, g_act_hi + a0 + kh + pA * 4);                                     \
    CP16(bb + DN_A + dA0l, g_act_lo + a0 + kh + pA * 4);                                     \
    CP16(bb + DN_A + dA1h, g_act_hi + a1 + kh + pA * 4);                                     \
    CP16(bb + DN_A + dA1l, g_act_lo + a1 + kh + pA * 4);                                     \
    size_t bro = dwb + (size_t)((s_) * 32 + kB) * 512 + (n0 >> 1) + pB * 4;                  \
    CP16(bb + DN_BH + dB, g_dwn_hi + bro);                                                   \
    CP16(bb + DN_BL + dB, g_dwn_lo + bro);                                                   \
} CP_COMMIT(); } while (0)

    float cd[2][4][4];
#pragma unroll
    for (int a = 0; a < 2; a++)
#pragma unroll
        for (int b = 0; b < 4; b++)
#pragma unroll
            for (int c = 0; c < 4; c++) cd[a][b][c] = 0.f;

    DN_ISSUE(0);
    DN_ISSUE(1);

#pragma unroll 1
    for (int it = 0; it < 32; ++it) {
        CP_WAIT1();
        __syncthreads();
        DN_ISSUE(it + 2);
        uint32_t base = dbase + (it % STAGES) * DN_STRIDE;
#pragma unroll
        for (int s = 0; s < 2; s++) {
            uint32_t ah[2][4], al[2][4];
#pragma unroll
            for (int mt = 0; mt < 2; mt++) {
                uint32_t row = mw * 32 + mt * 16 + (lane & 15);
                uint32_t co  = s * 32 + ((lane >> 4) << 4);
                ldsm4(ah[mt], base + DN_A + swz(row * 128 + co));
                ldsm4(al[mt], base + DN_A + swz(row * 128 + 64 + co));
            }
            uint32_t krow = s * 16 + (lane & 15);
            uint32_t ccol = nw * 64 + ((lane >> 4) << 4);
            uint32_t bh[8], bl[8];
#pragma unroll
            for (int h = 0; h < 2; h++) {
                ldsm4t(bh + 4 * h, base + DN_BH + swz(krow * 128 + ccol + h * 32));
                ldsm4t(bl + 4 * h, base + DN_BL + swz(krow * 128 + ccol + h * 32));
            }
#pragma unroll
            for (int mt = 0; mt < 2; mt++)
#pragma unroll
                for (int nf = 0; nf < 4; nf++) {
                    mma16816(cd[mt][nf], ah[mt], bh[2*nf], bh[2*nf+1]);
                    mma16816(cd[mt][nf], ah[mt], bl[2*nf], bl[2*nf+1]);
                    mma16816(cd[mt][nf], al[mt], bh[2*nf], bh[2*nf+1]);
                }
        }
    }
#undef DN_ISSUE

    const float* db = dnb + e * H_DIM;
#pragma unroll
    for (int mt = 0; mt < 2; mt++)
#pragma unroll
        for (int r = 0; r < 2; r++) {
            int slot = m0 + mw * 32 + mt * 16 + (lane >> 2) + r * 8;
            if (slot >= cnt) continue;
            int   tok = g_tok[e * T_TOK + slot];
            float w   = g_wt [e * T_TOK + slot];
            float* op = out + (size_t)tok * H_DIM;
#pragma unroll
            for (int nf = 0; nf < 4; nf++) {
                int col = n0 + nw * 32 + nf * 8 + (lane & 3) * 2;
                float v0 = (cd[mt][nf][2 * r]     + db[col])     * w;
                float v1 = (cd[mt][nf][2 * r + 1] + db[col + 1]) * w;
                atomicAdd(op + col,     v0);
                atomicAdd(op + col + 1, v1);
            }
        }
}

// ---------------- launch -----------------------------------------------------
extern "C" void kernel_launch(void* const* d_in, const int* in_sizes, int n_in,
                              void* d_out, int out_size) {
    const float* x   = (const float*)d_in[0];
    const float* rw  = (const float*)d_in[1];
    const float* rb  = (const float*)d_in[2];
    const float* gup = (const float*)d_in[3];
    const float* gub = (const float*)d_in[4];
    const float* dwn = (const float*)d_in[5];
    const float* dnb = (const float*)d_in[6];
    float* out = (float*)d_out;

    static bool attr_done = false;
    if (!attr_done) {
        cudaFuncSetAttribute(moe_gateup_hmma, cudaFuncAttributeMaxDynamicSharedMemorySize,
                             STAGES * GU_STRIDE + 1024);
        cudaFuncSetAttribute(moe_down_hmma, cudaFuncAttributeMaxDynamicSharedMemorySize,
                             STAGES * DN_STRIDE + 1024);
        attr_done = true;
    }

    uint32_t *xh, *xl, *gh, *gl, *dh, *dl;
    cudaGetSymbolAddress((void**)&xh, g_x_hi);   cudaGetSymbolAddress((void**)&xl, g_x_lo);
    cudaGetSymbolAddress((void**)&gh, g_gup_hi); cudaGetSymbolAddress((void**)&gl, g_gup_lo);
    cudaGetSymbolAddress((void**)&dh, g_dwn_hi); cudaGetSymbolAddress((void**)&dl, g_dwn_lo);

    zero_kernel<<<(T_TOK * H_DIM + 255) / 256, 256>>>(out);

    int n4x = T_TOK * H_DIM / 4;
    convert_kernel<<<(n4x + 255) / 256, 256>>>((const float4*)x, (uint2*)xh, (uint2*)xl, n4x);
    int n4g = N_EXP * H_DIM * 2 * I_DIM / 4;
    convert_kernel<<<(n4g + 255) / 256, 256>>>((const float4*)gup, (uint2*)gh, (uint2*)gl, n4g);
    int n4d = N_EXP * I_DIM * H_DIM / 4;
    convert_kernel<<<(n4d + 255) / 256, 256>>>((const float4*)dwn, (uint2*)dh, (uint2*)dl, n4d);

    router_kernel<<<T_TOK, 128>>>(x, rw, rb);

    dim3 g1(T_TOK / 128, I_DIM / 64, N_EXP);
    moe_gateup_hmma<<<g1, 256, STAGES * GU_STRIDE + 1024>>>(gub);

    dim3 g2(T_TOK / 128, H_DIM / 64, N_EXP);
    moe_down_hmma<<<g2, 256, STAGES * DN_STRIDE + 1024>>>(dnb, out);
}

// round 7
// speedup vs baseline: 3.8798x; 1.9317x over previous
#include <cuda_runtime.h>
#include <cstdint>
#include <math.h>

#define T_TOK 1024
#define H_DIM 1024
#define N_EXP 8
#define I_DIM 1024
#define ALPHA 1.702f
#define LIMIT 7.0f

// ---------------- device scratch (no allocations allowed) --------------------
__device__ int      g_cnt[N_EXP];
__device__ int      g_tok[N_EXP * T_TOK];
__device__ float    g_wt [N_EXP * T_TOK];
// fp16 operand planes, packed 2 elems per u32
__device__ __align__(16) uint32_t g_x_f16  [(size_t)T_TOK * H_DIM / 2];
__device__ __align__(16) uint32_t g_gup_f16[(size_t)N_EXP * H_DIM * 2 * I_DIM / 2];
__device__ __align__(16) uint32_t g_dwn_f16[(size_t)N_EXP * I_DIM * H_DIM / 2];
__device__ __align__(16) uint32_t g_act_f16[(size_t)N_EXP * T_TOK * I_DIM / 2];

// ---------------- helpers ----------------------------------------------------
__device__ __forceinline__ uint32_t smem_u32(const void* p) {
    uint32_t a;
    asm("{ .reg .u64 t; cvta.to.shared.u64 t, %1; cvt.u32.u64 %0, t; }"
        : "=r"(a) : "l"(p));
    return a;
}
__device__ __forceinline__ uint32_t swz128(uint32_t off) { return off ^ ((off >> 3) & 0x70); }
__device__ __forceinline__ uint32_t swz64 (uint32_t off) { return off ^ ((off >> 3) & 0x30); }

__device__ __forceinline__ uint32_t pack_f16x2(float a, float b) {
    uint32_t r;
    asm("cvt.rn.f16x2.f32 %0, %1, %2;" : "=r"(r) : "f"(b), "f"(a));  // a -> low half
    return r;
}

__device__ __forceinline__ void ldsm4(uint32_t* r, uint32_t a) {
    asm volatile("ldmatrix.sync.aligned.m8n8.x4.shared.b16 {%0,%1,%2,%3}, [%4];"
        : "=r"(r[0]), "=r"(r[1]), "=r"(r[2]), "=r"(r[3]) : "r"(a));
}
__device__ __forceinline__ void ldsm4t(uint32_t* r, uint32_t a) {
    asm volatile("ldmatrix.sync.aligned.m8n8.x4.trans.shared.b16 {%0,%1,%2,%3}, [%4];"
        : "=r"(r[0]), "=r"(r[1]), "=r"(r[2]), "=r"(r[3]) : "r"(a));
}
__device__ __forceinline__ void mma16816(float* c, const uint32_t* a, uint32_t b0, uint32_t b1) {
    asm volatile("mma.sync.aligned.m16n8k16.row.col.f32.f16.f16.f32 "
        "{%0,%1,%2,%3}, {%4,%5,%6,%7}, {%8,%9}, {%0,%1,%2,%3};"
        : "+f"(c[0]), "+f"(c[1]), "+f"(c[2]), "+f"(c[3])
        : "r"(a[0]), "r"(a[1]), "r"(a[2]), "r"(a[3]), "r"(b0), "r"(b1));
}

#define CP16(dst, src) \
    asm volatile("cp.async.cg.shared.global [%0], [%1], 16;" :: "r"(dst), "l"(src) : "memory")
#define CP_COMMIT() asm volatile("cp.async.commit_group;" ::: "memory")
#define CP_WAIT1()  asm volatile("cp.async.wait_group 1;" ::: "memory")

// ---------------- kernel: fp32 -> packed fp16 --------------------------------
__global__ void convert_kernel(const float4* __restrict__ src,
                               uint2* __restrict__ dst, int n4) {
    int i = blockIdx.x * blockDim.x + threadIdx.x;
    if (i >= n4) return;
    float4 v = src[i];
    dst[i] = make_uint2(pack_f16x2(v.x, v.y), pack_f16x2(v.z, v.w));
}

// ---------------- kernel 0: zero ---------------------------------------------
__global__ void zero_kernel(float* __restrict__ out) {
    int i = blockIdx.x * blockDim.x + threadIdx.x;
    if (i < T_TOK * H_DIM) out[i] = 0.0f;
    if (i < N_EXP) g_cnt[i] = 0;
}

// ---------------- kernel 1: router -------------------------------------------
__global__ void router_kernel(const float* __restrict__ x,
                              const float* __restrict__ rw,
                              const float* __restrict__ rb) {
    const int t = blockIdx.x;
    __shared__ float s[N_EXP][128];
    float p[N_EXP];
#pragma unroll
    for (int e = 0; e < N_EXP; e++) p[e] = 0.0f;
    const float* xr = x + (size_t)t * H_DIM;
    for (int h = threadIdx.x; h < H_DIM; h += 128) {
        float xv = xr[h];
#pragma unroll
        for (int e = 0; e < N_EXP; e++) p[e] += xv * rw[e * H_DIM + h];
    }
#pragma unroll
    for (int e = 0; e < N_EXP; e++) s[e][threadIdx.x] = p[e];
    __syncthreads();
    if (threadIdx.x == 0) {
        float l[N_EXP], mx = -1e30f;
#pragma unroll
        for (int e = 0; e < N_EXP; e++) {
            float sum = 0.0f;
            for (int i = 0; i < 128; i++) sum += s[e][i];
            l[e] = sum + rb[e];
            mx = fmaxf(mx, l[e]);
        }
        float den = 0.0f, sc[N_EXP];
#pragma unroll
        for (int e = 0; e < N_EXP; e++) { sc[e] = expf(l[e] - mx); den += sc[e]; }
        float inv = 1.0f / den;
#pragma unroll
        for (int e = 0; e < N_EXP; e++) sc[e] *= inv;
        int i0 = 0;
#pragma unroll
        for (int e = 1; e < N_EXP; e++) if (sc[e] > sc[i0]) i0 = e;
        int i1 = (i0 == 0) ? 1 : 0;
#pragma unroll
        for (int e = 0; e < N_EXP; e++) if (e != i0 && sc[e] > sc[i1]) i1 = e;
        int p0 = atomicAdd(&g_cnt[i0], 1);
        g_tok[i0 * T_TOK + p0] = t; g_wt[i0 * T_TOK + p0] = sc[i0];
        int p1 = atomicAdd(&g_cnt[i1], 1);
        g_tok[i1 * T_TOK + p1] = t; g_wt[i1 * T_TOK + p1] = sc[i1];
    }
}

// ---------------- kernel 2: gate_up HMMA (fp16, cp.async 3-stage) ------------
// Stage (16KB): A 8KB (128 rows x 64B, SW64), BG 4KB, BU 4KB (32 k-rows x 128B, SW128)
#define GU_A      0
#define GU_BG     8192
#define GU_BU     12288
#define GU_STRIDE 16384
#define STAGES    3

__global__ __launch_bounds__(256, 2)
void moe_gateup_hmma(const float* __restrict__ gub) {
    const int e   = blockIdx.z;
    const int cnt = g_cnt[e];
    const int m0  = blockIdx.x * 128;
    if (m0 >= cnt) return;
    const int n0  = blockIdx.y * 64;

    extern __shared__ char dsm[];
    __shared__ int s_tok[128];
    const uint32_t dbase = (smem_u32(dsm) + 1023u) & ~1023u;

    const int tid = threadIdx.x, lane = tid & 31, wid = tid >> 5;
    const int mw = wid >> 1, nw = wid & 1;

    if (tid < 128) {
        int gm = m0 + tid;
        s_tok[tid] = (gm < cnt) ? g_tok[e * T_TOK + gm] : g_tok[e * T_TOK];
    }
    __syncthreads();

    const int rA = tid >> 2, pA = tid & 3;       // A: rows rA, rA+64; 16B chunk pA
    const int tA0 = s_tok[rA], tA1 = s_tok[rA + 64];
    const int kB = tid >> 3, pB = tid & 7;       // B: k-row kB; 16B chunk pB
    const size_t gupb = (size_t)e * (H_DIM * I_DIM);      // u32/plane-row: 1024
    const uint32_t dA0 = swz64(rA * 64 + pA * 16);
    const uint32_t dA1 = swz64((rA + 64) * 64 + pA * 16);
    const uint32_t dB  = swz128(kB * 128 + pB * 16);

#define GU_ISSUE(s_) do { if ((s_) < 32) {                                                   \
    uint32_t bb = dbase + ((s_) % STAGES) * GU_STRIDE;                                       \
    int kh = (s_) * 16;                                                                      \
    CP16(bb + GU_A + dA0, g_x_f16 + (size_t)tA0 * 512 + kh + pA * 4);                        \
    CP16(bb + GU_A + dA1, g_x_f16 + (size_t)tA1 * 512 + kh + pA * 4);                        \
    size_t bro = gupb + (size_t)((s_) * 32 + kB) * 1024 + (n0 >> 1) + pB * 4;                \
    CP16(bb + GU_BG + dB, g_gup_f16 + bro);                                                  \
    CP16(bb + GU_BU + dB, g_gup_f16 + bro + 512);                                            \
} CP_COMMIT(); } while (0)

    float cg[2][4][4], cu[2][4][4];
#pragma unroll
    for (int a = 0; a < 2; a++)
#pragma unroll
        for (int b = 0; b < 4; b++)
#pragma unroll
            for (int c = 0; c < 4; c++) { cg[a][b][c] = 0.f; cu[a][b][c] = 0.f; }

    GU_ISSUE(0);
    GU_ISSUE(1);

#pragma unroll 1
    for (int it = 0; it < 32; ++it) {
        CP_WAIT1();
        __syncthreads();
        GU_ISSUE(it + 2);
        uint32_t base = dbase + (it % STAGES) * GU_STRIDE;
#pragma unroll
        for (int s = 0; s < 2; s++) {
            uint32_t am[2][4];
#pragma unroll
            for (int mt = 0; mt < 2; mt++) {
                uint32_t row = mw * 32 + mt * 16 + (lane & 15);
                uint32_t co  = s * 32 + ((lane >> 4) << 4);
                ldsm4(am[mt], base + GU_A + swz64(row * 64 + co));
            }
            uint32_t krow = s * 16 + (lane & 15);
            uint32_t ccol = nw * 64 + ((lane >> 4) << 4);
            uint32_t bg[8], bu[8];
#pragma unroll
            for (int h = 0; h < 2; h++) {
                ldsm4t(bg + 4 * h, base + GU_BG + swz128(krow * 128 + ccol + h * 32));
                ldsm4t(bu + 4 * h, base + GU_BU + swz128(krow * 128 + ccol + h * 32));
            }
#pragma unroll
            for (int mt = 0; mt < 2; mt++)
#pragma unroll
                for (int nf = 0; nf < 4; nf++) {
                    mma16816(cg[mt][nf], am[mt], bg[2*nf], bg[2*nf+1]);
                    mma16816(cu[mt][nf], am[mt], bu[2*nf], bu[2*nf+1]);
                }
        }
    }
#undef GU_ISSUE

    // epilogue: bias + clamped GLU -> g_act (packed fp16)
    const float* gb = gub + e * 2 * I_DIM;
#pragma unroll
    for (int mt = 0; mt < 2; mt++)
#pragma unroll
        for (int r = 0; r < 2; r++) {
            int slot = m0 + mw * 32 + mt * 16 + (lane >> 2) + r * 8;
            if (slot >= cnt) continue;
            size_t abase = ((size_t)(e * T_TOK + slot) * I_DIM) >> 1;
#pragma unroll
            for (int nf = 0; nf < 4; nf++) {
                int col = n0 + nw * 32 + nf * 8 + (lane & 3) * 2;
                float g0 = cg[mt][nf][2 * r]     + gb[col];
                float g1 = cg[mt][nf][2 * r + 1] + gb[col + 1];
                float u0 = cu[mt][nf][2 * r]     + gb[I_DIM + col];
                float u1 = cu[mt][nf][2 * r + 1] + gb[I_DIM + col + 1];
                g0 = fminf(g0, LIMIT); g1 = fminf(g1, LIMIT);
                u0 = fminf(fmaxf(u0, -LIMIT), LIMIT);
                u1 = fminf(fmaxf(u1, -LIMIT), LIMIT);
                float a0 = (u0 + 1.0f) * (g0 / (1.0f + __expf(-ALPHA * g0)));
                float a1 = (u1 + 1.0f) * (g1 / (1.0f + __expf(-ALPHA * g1)));
                g_act_f16[abase + (col >> 1)] = pack_f16x2(a0, a1);
            }
        }
}

// ---------------- kernel 3: down HMMA (fp16, cp.async 3-stage) ---------------
// Stage (12KB): A 8KB (SW64), B 4KB (SW128)
#define DN_A      0
#define DN_B      8192
#define DN_STRIDE 12288

__global__ __launch_bounds__(256, 2)
void moe_down_hmma(const float* __restrict__ dnb, float* __restrict__ out) {
    const int e   = blockIdx.z;
    const int cnt = g_cnt[e];
    const int m0  = blockIdx.x * 128;
    if (m0 >= cnt) return;
    const int n0  = blockIdx.y * 64;

    extern __shared__ char dsm[];
    const uint32_t dbase = (smem_u32(dsm) + 1023u) & ~1023u;

    const int tid = threadIdx.x, lane = tid & 31, wid = tid >> 5;
    const int mw = wid >> 1, nw = wid & 1;

    const int rA = tid >> 2, pA = tid & 3;
    const int kB = tid >> 3, pB = tid & 7;
    const size_t a0 = (size_t)(e * T_TOK + m0 + rA) * 512;
    const size_t a1 = (size_t)(e * T_TOK + m0 + rA + 64) * 512;
    const size_t dwb = (size_t)e * (I_DIM * H_DIM / 2);
    const uint32_t dA0 = swz64(rA * 64 + pA * 16);
    const uint32_t dA1 = swz64((rA + 64) * 64 + pA * 16);
    const uint32_t dB  = swz128(kB * 128 + pB * 16);

#define DN_ISSUE(s_) do { if ((s_) < 32) {                                                   \
    uint32_t bb = dbase + ((s_) % STAGES) * DN_STRIDE;                                       \
    int kh = (s_) * 16;                                                                      \
    CP16(bb + DN_A + dA0, g_act_f16 + a0 + kh + pA * 4);                                     \
    CP16(bb + DN_A + dA1, g_act_f16 + a1 + kh + pA * 4);                                     \
    size_t bro = dwb + (size_t)((s_) * 32 + kB) * 512 + (n0 >> 1) + pB * 4;                  \
    CP16(bb + DN_B + dB, g_dwn_f16 + bro);                                                   \
} CP_COMMIT(); } while (0)

    float cd[2][4][4];
#pragma unroll
    for (int a = 0; a < 2; a++)
#pragma unroll
        for (int b = 0; b < 4; b++)
#pragma unroll
            for (int c = 0; c < 4; c++) cd[a][b][c] = 0.f;

    DN_ISSUE(0);
    DN_ISSUE(1);

#pragma unroll 1
    for (int it = 0; it < 32; ++it) {
        CP_WAIT1();
        __syncthreads();
        DN_ISSUE(it + 2);
        uint32_t base = dbase + (it % STAGES) * DN_STRIDE;
#pragma unroll
        for (int s = 0; s < 2; s++) {
            uint32_t am[2][4];
#pragma unroll
            for (int mt = 0; mt < 2; mt++) {
                uint32_t row = mw * 32 + mt * 16 + (lane & 15);
                uint32_t co  = s * 32 + ((lane >> 4) << 4);
                ldsm4(am[mt], base + DN_A + swz64(row * 64 + co));
            }
            uint32_t krow = s * 16 + (lane & 15);
            uint32_t ccol = nw * 64 + ((lane >> 4) << 4);
            uint32_t bb[8];
#pragma unroll
            for (int h = 0; h < 2; h++)
                ldsm4t(bb + 4 * h, base + DN_B + swz128(krow * 128 + ccol + h * 32));
#pragma unroll
            for (int mt = 0; mt < 2; mt++)
#pragma unroll
                for (int nf = 0; nf < 4; nf++)
                    mma16816(cd[mt][nf], am[mt], bb[2*nf], bb[2*nf+1]);
        }
    }
#undef DN_ISSUE

    const float* db = dnb + e * H_DIM;
#pragma unroll
    for (int mt = 0; mt < 2; mt++)
#pragma unroll
        for (int r = 0; r < 2; r++) {
            int slot = m0 + mw * 32 + mt * 16 + (lane >> 2) + r * 8;
            if (slot >= cnt) continue;
            int   tok = g_tok[e * T_TOK + slot];
            float w   = g_wt [e * T_TOK + slot];
            float* op = out + (size_t)tok * H_DIM;
#pragma unroll
            for (int nf = 0; nf < 4; nf++) {
                int col = n0 + nw * 32 + nf * 8 + (lane & 3) * 2;
                float v0 = (cd[mt][nf][2 * r]     + db[col])     * w;
                float v1 = (cd[mt][nf][2 * r + 1] + db[col + 1]) * w;
                atomicAdd(op + col,     v0);
                atomicAdd(op + col + 1, v1);
            }
        }
}

// ---------------- launch -----------------------------------------------------
extern "C" void kernel_launch(void* const* d_in, const int* in_sizes, int n_in,
                              void* d_out, int out_size) {
    const float* x   = (const float*)d_in[0];
    const float* rw  = (const float*)d_in[1];
    const float* rb  = (const float*)d_in[2];
    const float* gup = (const float*)d_in[3];
    const float* gub = (const float*)d_in[4];
    const float* dwn = (const float*)d_in[5];
    const float* dnb = (const float*)d_in[6];
    float* out = (float*)d_out;

    static bool attr_done = false;
    if (!attr_done) {
        cudaFuncSetAttribute(moe_gateup_hmma, cudaFuncAttributeMaxDynamicSharedMemorySize,
                             STAGES * GU_STRIDE + 1024);
        cudaFuncSetAttribute(moe_down_hmma, cudaFuncAttributeMaxDynamicSharedMemorySize,
                             STAGES * DN_STRIDE + 1024);
        attr_done = true;
    }

    uint32_t *xf, *gf, *df;
    cudaGetSymbolAddress((void**)&xf, g_x_f16);
    cudaGetSymbolAddress((void**)&gf, g_gup_f16);
    cudaGetSymbolAddress((void**)&df, g_dwn_f16);

    zero_kernel<<<(T_TOK * H_DIM + 255) / 256, 256>>>(out);

    int n4x = T_TOK * H_DIM / 4;
    convert_kernel<<<(n4x + 255) / 256, 256>>>((const float4*)x, (uint2*)xf, n4x);
    int n4g = N_EXP * H_DIM * 2 * I_DIM / 4;
    convert_kernel<<<(n4g + 255) / 256, 256>>>((const float4*)gup, (uint2*)gf, n4g);
    int n4d = N_EXP * I_DIM * H_DIM / 4;
    convert_kernel<<<(n4d + 255) / 256, 256>>>((const float4*)dwn, (uint2*)df, n4d);

    router_kernel<<<T_TOK, 128>>>(x, rw, rb);

    dim3 g1(T_TOK / 128, I_DIM / 64, N_EXP);
    moe_gateup_hmma<<<g1, 256, STAGES * GU_STRIDE + 1024>>>(gub);

    dim3 g2(T_TOK / 128, H_DIM / 64, N_EXP);
    moe_down_hmma<<<g2, 256, STAGES * DN_STRIDE + 1024>>>(dnb, out);
}